// round 5
// baseline (speedup 1.0000x reference)
#include <cuda_runtime.h>
#include <cstddef>

#define HDIM  512
#define TDIM  1024
#define TPB2  256            // fast kernel threads
#define NW2   (TPB2 / 32)    // 8 warps
#define CH2   (TDIM / TPB2)  // 4 t-values per thread in scans
#define HPT   (HDIM / TPB2)  // 2 h-values per thread
#define TPBS  128            // slow kernel threads
#define SLOWG 64             // slow kernel blocks
#define RPT   (HDIM / TPBS)  // 4
#define NWS   (TPBS / 32)
#define TWO_PI_F 6.283185307179586476925286766559f
#define CINF  3.402823466e38f
#define FULLM 0xffffffffu

// Sticky violation flags: zero at module load; only ever written to 1.
// .x = W_h not identity, .y = b_x nonzero. Single LDG.64 in the fallback.
__device__ int2 g_flags;

__device__ __forceinline__ float warp_sum(float v) {
    #pragma unroll
    for (int o = 16; o; o >>= 1) v += __shfl_xor_sync(FULLM, v, o);
    return v;
}

// ---------------------------------------------------------------------------
// Fast kernel: one block per batch element. Performs distributed W_h / b_x
// checks (sticky flags) and computes the fast closed form speculatively; the
// fallback kernel overwrites out only if a check tripped.
//
// Math: with W_h==I, b_x==0:  h_t = X_t*wx - M_t,
//   M_t = min(a, wx*Cmin_t) for wx>=0 else min(a, wx*Cmax_t),  a = -h0,
// where X = cumsum(x), Cmin/Cmax = prefix min/max of X. R_t = sum_h M_t*wk
// changes only at prefix-record times. out = X_t*<wx,wk> - R_t + b_out.
// ---------------------------------------------------------------------------
__global__ void __launch_bounds__(TPB2) rnn_fast_kernel(
    const float* __restrict__ x,       // [B, T]
    const float* __restrict__ theta0,  // [B]
    const float* __restrict__ W_h,     // [H, H]
    const float* __restrict__ W_x,     // [H]
    const float* __restrict__ b_x,     // [H]
    const float* __restrict__ W_h0,    // [H]
    const float* __restrict__ b_h0,    // [H]
    const float* __restrict__ W_out,   // [2, H]
    const float* __restrict__ b_out,   // [2]
    float* __restrict__ out,           // [T+1, B, 2]
    int B, int T, int H, int fastOK)
{
    __shared__ float  sX[TDIM + 1];
    __shared__ int    sSeg[TDIM + 1];
    __shared__ float  sRecCmin[TDIM + 1];
    __shared__ float  sRecCmax[TDIM + 1];
    __shared__ float2 sRrec[TDIM + 1];
    __shared__ float  swx[HDIM], sa[HDIM], sw0[HDIM], sw1[HDIM];
    __shared__ float  sS[NW2], sMn[NW2], sMx[NW2];
    __shared__ int    sScrI[NW2];
    __shared__ int    snrec;
    __shared__ float  sDred[NW2 * 2];

    const int b    = blockIdx.x;
    const int tid  = threadIdx.x;
    const int lane = tid & 31;
    const int warp = tid >> 5;
    const float INF = __int_as_float(0x7f800000);

    // ---- Prefetch (issued before the check loop so latency overlaps) ----
    float th = 0.f, b0 = 0.f, b1 = 0.f;
    float rwx[HPT], rw0[HPT], rw1[HPT], ra[HPT];
    float4 xv = make_float4(0.f, 0.f, 0.f, 0.f);
    if (fastOK) {
        th = theta0[b] * TWO_PI_F;
        b0 = b_out[0];
        b1 = b_out[1];
        xv = reinterpret_cast<const float4*>(x + (size_t)b * TDIM)[tid];
        #pragma unroll
        for (int r = 0; r < HPT; r++) {
            const int h = r * TPB2 + tid;
            rwx[r] = W_x[h];
            rw0[r] = W_out[h];
            rw1[r] = W_out[HDIM + h];
            ra[r]  = -fmaf(th, W_h0[h], b_h0[h]);   // a = -h0
        }
    }

    // ---- Distributed identity / zero checks ----
    {
        const int n  = H * H;
        const int n4 = n >> 2;
        const float4* W4 = reinterpret_cast<const float4*>(W_h);
        for (int i4 = b * TPB2 + tid; i4 < n4; i4 += gridDim.x * TPB2) {
            const float4 v = W4[i4];
            const int e = i4 << 2;
            const int r = e / H;
            const int c = e - r * H;
            const float e0 = (c     == r) ? 1.f : 0.f;
            const float e1 = (c + 1 == r) ? 1.f : 0.f;
            const float e2 = (c + 2 == r) ? 1.f : 0.f;
            const float e3 = (c + 3 == r) ? 1.f : 0.f;
            if (v.x != e0 || v.y != e1 || v.z != e2 || v.w != e3)
                g_flags.x = 1;
        }
        if (b == 0) {
            for (int i = (n4 << 2) + tid; i < n; i += TPB2) {
                const int r = i / H, c = i - r * H;
                if (W_h[i] != ((r == c) ? 1.f : 0.f)) g_flags.x = 1;
            }
            for (int i = tid; i < H; i += TPB2)
                if (b_x[i] != 0.0f) g_flags.y = 1;
        }
    }

    if (!fastOK) return;   // fallback kernel does everything

    // ---- Fused triple scan: (sum, prefix-min, prefix-max) of cumsum(x) ----
    float lx[CH2], lmn[CH2], lmx[CH2];
    float Xoff, Omn, Omx;
    {
        lx[0] = xv.x;
        lx[1] = lx[0] + xv.y;
        lx[2] = lx[1] + xv.z;
        lx[3] = lx[2] + xv.w;
        float mn = lx[0], mx = lx[0];
        lmn[0] = mn; lmx[0] = mx;
        #pragma unroll
        for (int j = 1; j < CH2; j++) {
            mn = fminf(mn, lx[j]); lmn[j] = mn;
            mx = fmaxf(mx, lx[j]); lmx[j] = mx;
        }
        // warp-inclusive scan of (S, m, M) under the prefix monoid
        float S = lx[CH2 - 1], m = mn, M = mx;
        #pragma unroll
        for (int o = 1; o < 32; o <<= 1) {
            const float sL = __shfl_up_sync(FULLM, S, o);
            const float mL = __shfl_up_sync(FULLM, m, o);
            const float ML = __shfl_up_sync(FULLM, M, o);
            if (lane >= o) {
                m = fminf(mL, sL + m);
                M = fmaxf(ML, sL + M);
                S = sL + S;
            }
        }
        if (lane == 31) { sS[warp] = S; sMn[warp] = m; sMx[warp] = M; }
        __syncthreads();
        // block-exclusive prefix over warp aggregates
        float bS = 0.f, bMn = CINF, bMx = -CINF;
        for (int w = 0; w < warp; w++) {
            bMn = fminf(bMn, bS + sMn[w]);
            bMx = fmaxf(bMx, bS + sMx[w]);
            bS += sS[w];
        }
        // lane-exclusive within warp
        float eS = __shfl_up_sync(FULLM, S, 1);
        float eMn = __shfl_up_sync(FULLM, m, 1);
        float eMx = __shfl_up_sync(FULLM, M, 1);
        if (lane == 0) { eS = 0.f; eMn = CINF; eMx = -CINF; }
        Xoff = bS + eS;
        Omn  = fminf(bMn, bS + eMn);
        Omx  = fmaxf(bMx, bS + eMx);
    }

    // per-element prefix values + record flags (all in registers)
    float cmn[CH2], cmx[CH2];
    int   rec[CH2];
    {
        float pm = Omn, pM = Omx;
        #pragma unroll
        for (int j = 0; j < CH2; j++) {
            lx[j] += Xoff;
            cmn[j] = fminf(pm, lx[j]);
            cmx[j] = fmaxf(pM, lx[j]);
            rec[j] = (cmn[j] < pm) || (cmx[j] > pM);
            pm = cmn[j]; pM = cmx[j];
            sX[tid * CH2 + j + 1] = lx[j];
        }
        if (tid == 0) sX[0] = 0.f;
    }

    // ---- record-count scan -> segment ids ----
    {
        int lc[CH2];
        int c = 0;
        #pragma unroll
        for (int j = 0; j < CH2; j++) { c += rec[j]; lc[j] = c; }
        int wc = c;
        #pragma unroll
        for (int o = 1; o < 32; o <<= 1) {
            const int u = __shfl_up_sync(FULLM, wc, o);
            if (lane >= o) wc += u;
        }
        if (lane == 31) sScrI[warp] = wc;
        __syncthreads();
        int off = 0;
        for (int w = 0; w < warp; w++) off += sScrI[w];
        const int lp = __shfl_up_sync(FULLM, wc, 1);
        if (lane > 0) off += lp;
        #pragma unroll
        for (int j = 0; j < CH2; j++) {
            const int t = tid * CH2 + j + 1;
            const int rid = lc[j] + off;
            sSeg[t] = rid;
            if (rec[j]) {                // scatter record values
                sRecCmin[rid] = cmn[j];
                sRecCmax[rid] = cmx[j];
            }
        }
        if (tid == TPB2 - 1) snrec = lc[CH2 - 1] + off;
    }
    if (tid == 0) {
        sRecCmin[0] = INF;     // sentinel: min(a, wx*INF)=a (NaN-safe, wx==0)
        sRecCmax[0] = -INF;
        sSeg[0] = 0;
    }

    // ---- stage per-h data (register -> smem; loads already done) ----
    #pragma unroll
    for (int r = 0; r < HPT; r++) {
        const int h = r * TPB2 + tid;
        swx[h] = rwx[r];
        sa[h]  = ra[r];
        sw0[h] = rw0[r];
        sw1[h] = rw1[r];
    }
    __syncthreads();

    // ---- R at each record (two records per warp iteration) ----
    const int nrec = snrec;
    for (int r = warp; r <= nrec; r += 2 * NW2) {
        const int  r2 = r + NW2;
        const bool h2 = (r2 <= nrec);
        const float cm0 = sRecCmin[r],  cx0 = sRecCmax[r];
        const float cm1 = h2 ? sRecCmin[r2] : 0.f;
        const float cx1 = h2 ? sRecCmax[r2] : 0.f;
        float p00 = 0.f, p01 = 0.f, p10 = 0.f, p11 = 0.f;
        #pragma unroll
        for (int i = 0; i < HDIM / 32; i++) {
            const int h = i * 32 + lane;
            const float wx = swx[h], a = sa[h];
            const float w0 = sw0[h], w1 = sw1[h];
            const float m0 = fminf(a, wx * ((wx >= 0.f) ? cm0 : cx0));
            p00 = fmaf(m0, w0, p00);
            p01 = fmaf(m0, w1, p01);
            const float m1 = fminf(a, wx * ((wx >= 0.f) ? cm1 : cx1));
            p10 = fmaf(m1, w0, p10);
            p11 = fmaf(m1, w1, p11);
        }
        #pragma unroll
        for (int o = 16; o; o >>= 1) {
            p00 += __shfl_xor_sync(FULLM, p00, o);
            p01 += __shfl_xor_sync(FULLM, p01, o);
            p10 += __shfl_xor_sync(FULLM, p10, o);
            p11 += __shfl_xor_sync(FULLM, p11, o);
        }
        if (lane == 0) {
            sRrec[r] = make_float2(p00, p01);
            if (h2) sRrec[r2] = make_float2(p10, p11);
        }
    }

    // ---- dots <wx,w0>, <wx,w1> ----
    {
        float d0 = 0.f, d2 = 0.f;
        #pragma unroll
        for (int r = 0; r < HPT; r++) {
            d0 = fmaf(rwx[r], rw0[r], d0);
            d2 = fmaf(rwx[r], rw1[r], d2);
        }
        d0 = warp_sum(d0);
        d2 = warp_sum(d2);
        if (lane == 0) { sDred[warp * 2] = d0; sDred[warp * 2 + 1] = d2; }
    }
    __syncthreads();

    float D0 = 0.f, D2 = 0.f;
    #pragma unroll
    for (int w = 0; w < NW2; w++) { D0 += sDred[w * 2]; D2 += sDred[w * 2 + 1]; }

    // ---- emit outputs ----
    for (int t = tid; t <= TDIM; t += TPB2) {
        const float2 R = sRrec[sSeg[t]];
        const float  X = sX[t];
        float2 o;
        o.x = fmaf(X, D0, b0) - R.x;
        o.y = fmaf(X, D2, b1) - R.y;
        reinterpret_cast<float2*>(out)[(size_t)t * B + b] = o;
    }
}

// ---------------------------------------------------------------------------
// Fallback: only does work if a guard tripped (or unexpected shapes).
// Single LDG.64 flag read; SLOWG blocks each cover B/SLOWG batches.
// ---------------------------------------------------------------------------
__global__ void __launch_bounds__(TPBS) rnn_slow_kernel(
    const float* __restrict__ x,
    const float* __restrict__ theta0,
    const float* __restrict__ W_h,
    const float* __restrict__ W_x,
    const float* __restrict__ b_x,
    const float* __restrict__ W_h0,
    const float* __restrict__ b_h0,
    const float* __restrict__ W_out,
    const float* __restrict__ b_out,
    float* __restrict__ out,
    int B, int T, int fastOK)
{
    const int2 f = g_flags;
    if (fastOK && f.x == 0 && f.y == 0) return;
    const int nid = f.x;

    __shared__ float2 sred[NWS];
    __shared__ float hbuf[2][HDIM];

    const int tid  = threadIdx.x;
    const int lane = tid & 31;
    const int warp = tid >> 5;
    const float b0 = b_out[0], b1 = b_out[1];

    for (int b = blockIdx.x; b < B; b += gridDim.x) {
        const float th = theta0[b] * TWO_PI_F;

        float wx[RPT], bx[RPT], w0[RPT], w1[RPT], h[RPT];
        #pragma unroll
        for (int r = 0; r < RPT; r++) {
            const int hh = r * TPBS + tid;
            wx[r] = W_x[hh];
            bx[r] = b_x[hh];
            w0[r] = W_out[hh];
            w1[r] = W_out[HDIM + hh];
            h[r]  = fmaf(th, W_h0[hh], b_h0[hh]);
            hbuf[0][hh] = h[r];
        }
        __syncthreads();

        // t = 0 row
        {
            float p0 = 0.f, p1 = 0.f;
            #pragma unroll
            for (int r = 0; r < RPT; r++) {
                p0 = fmaf(h[r], w0[r], p0);
                p1 = fmaf(h[r], w1[r], p1);
            }
            p0 = warp_sum(p0); p1 = warp_sum(p1);
            if (lane == 0) sred[warp] = make_float2(p0, p1);
            __syncthreads();
            if (tid == 0) {
                float o0 = b0, o1 = b1;
                for (int w = 0; w < NWS; w++) { o0 += sred[w].x; o1 += sred[w].y; }
                reinterpret_cast<float2*>(out)[b] = make_float2(o0, o1);
            }
            __syncthreads();
        }

        int cur = 0;
        for (int t = 0; t < T; t++) {
            const float xt = __ldg(&x[(size_t)b * T + t]);
            float acc[RPT];
            #pragma unroll
            for (int r = 0; r < RPT; r++) acc[r] = fmaf(xt, wx[r], bx[r]);

            if (!nid) {
                #pragma unroll
                for (int r = 0; r < RPT; r++) acc[r] += h[r];
            } else {
                const float* hs = hbuf[cur];
                for (int k = 0; k < HDIM; k++) {
                    const float hk = hs[k];
                    #pragma unroll
                    for (int r = 0; r < RPT; r++)
                        acc[r] = fmaf(W_h[(size_t)(r * TPBS + tid) * HDIM + k], hk, acc[r]);
                }
            }
            float p0 = 0.f, p1 = 0.f;
            #pragma unroll
            for (int r = 0; r < RPT; r++) {
                h[r] = fmaxf(acc[r], 0.f);
                if (nid) hbuf[1 - cur][r * TPBS + tid] = h[r];
                p0 = fmaf(h[r], w0[r], p0);
                p1 = fmaf(h[r], w1[r], p1);
            }
            p0 = warp_sum(p0); p1 = warp_sum(p1);
            if (lane == 0) sred[warp] = make_float2(p0, p1);
            __syncthreads();
            if (tid == 0) {
                float o0 = b0, o1 = b1;
                for (int w = 0; w < NWS; w++) { o0 += sred[w].x; o1 += sred[w].y; }
                reinterpret_cast<float2*>(out)[(size_t)(t + 1) * B + b] = make_float2(o0, o1);
            }
            __syncthreads();
            cur ^= 1;
        }
        __syncthreads();
    }
}

// ---------------------------------------------------------------------------
extern "C" void kernel_launch(void* const* d_in, const int* in_sizes, int n_in,
                              void* d_out, int out_size)
{
    const float* x     = (const float*)d_in[0];
    const float* th0   = (const float*)d_in[1];
    const float* W_h   = (const float*)d_in[2];
    const float* W_x   = (const float*)d_in[3];
    const float* b_x   = (const float*)d_in[4];
    const float* W_h0  = (const float*)d_in[5];
    const float* b_h0  = (const float*)d_in[6];
    const float* W_out = (const float*)d_in[7];
    const float* b_out = (const float*)d_in[8];

    const int H   = in_sizes[4];           // 512
    const int NAV = in_sizes[8] / 2;       // 1
    const int B   = in_sizes[1] / NAV;     // 256
    const int I   = in_sizes[3] / H;       // 1
    const int T   = in_sizes[0] / (B * I); // 1024

    const int fastOK = (H == HDIM && T == TDIM) ? 1 : 0;

    rnn_fast_kernel<<<B, TPB2>>>(x, th0, W_h, W_x, b_x, W_h0, b_h0,
                                 W_out, b_out, (float*)d_out, B, T, H, fastOK);

    rnn_slow_kernel<<<SLOWG, TPBS>>>(x, th0, W_h, W_x, b_x, W_h0, b_h0,
                                     W_out, b_out, (float*)d_out, B, T, fastOK);
}